// round 7
// baseline (speedup 1.0000x reference)
#include <cuda_runtime.h>
#include <cuda_bf16.h>

// YOLOv1 loss, GB300 — sparse, warp-per-batch, vectorized box-region loads.
// preds: (BSZ, 7, 7, 90) fp32   gt_boxes: (BSZ, 8, 4) fp32   gt_labels: (BSZ, 8) int32
// out: scalar fp32 total loss.

#define SS      7
#define NB      2
#define NC      80
#define NGT     8
#define FEAT    90
#define CELLS   49
#define NPRED   98
#define WPB     8                // warps per block, one batch element each
#define TPB     (WPB * 32)
#define MAX_BLK 1024

static __device__ double       g_partials[MAX_BLK];
static __device__ unsigned int g_count = 0;

struct BT {                       // per-batch targets (one per warp)
    float         conf_t[NPRED];  // 0 when no object
    float         coord[NGT][4];
    int           cell[NGT];
    unsigned int  cmask[NGT][3];  // 96-bit class one-hot union
    unsigned char hit[NPRED];     // 0 = no obj, else coord idx+1
    unsigned char cellmap[CELLS]; // 0 = unused, else cell idx+1
    int           n_cell;
    // per-GT scratch
    int   gi[NGT], gj[NGT], best[NGT], lab[NGT];
    float iou[NGT], cv[NGT][4];
};

__global__ __launch_bounds__(TPB, 6) void yolo_fused(
    const float* __restrict__ preds,
    const float* __restrict__ gt_boxes,
    const int*   __restrict__ gt_labels,
    float*       __restrict__ out,
    int Bsz)
{
    const int w    = threadIdx.x >> 5;
    const int lane = threadIdx.x & 31;
    const int bz   = blockIdx.x * WPB + w;

    __shared__ BT     bt[WPB];
    __shared__ double s_part[WPB];
    __shared__ bool   s_last;

    float acc = 0.f;
    const bool active = (bz < Bsz);
    BT& T = bt[w];
    const float* p = preds + (size_t)bz * (CELLS * FEAT);

    // ---- hoist GT loads (DRAM latency overlaps the zeroing below) ----
    float4 g4 = make_float4(0.f, 0.f, 0.f, 0.f);
    int lab = 0;
    if (active && lane < NGT) {
        g4  = __ldg(reinterpret_cast<const float4*>(gt_boxes) + (size_t)bz * NGT + lane);
        lab = __ldg(gt_labels + bz * NGT + lane);
    }

    if (active) {
        // ---- zero target maps (full warp) ----
        for (int i = lane; i < NPRED; i += 32) { T.conf_t[i] = 0.f; T.hit[i] = 0; }
        for (int i = lane; i < CELLS; i += 32) T.cellmap[i] = 0;

        // ---- phase 1: per-GT geometry + IoU (lanes 0..7) ----
        if (lane < NGT) {
            const float x1 = g4.x, y1 = g4.y, x2 = g4.z, y2 = g4.w;
            const float cx = (x1 + x2) * 0.5f, cy = (y1 + y2) * 0.5f;
            const float bw = x2 - x1, bh = y2 - y1;
            int gi = (int)(cx * (float)SS); gi = min(max(gi, 0), SS - 1);
            int gj = (int)(cy * (float)SS); gj = min(max(gj, 0), SS - 1);

            const float* pc = p + (gj * SS + gi) * FEAT;
            float pb[2][4];
            #pragma unroll
            for (int b = 0; b < 2; b++) {        // 8 independent scalar LDGs
                pb[b][0] = __ldg(pc + b * 5 + 0);
                pb[b][1] = __ldg(pc + b * 5 + 1);
                pb[b][2] = __ldg(pc + b * 5 + 2);
                pb[b][3] = __ldg(pc + b * 5 + 3);
            }
            float ious[2];
            #pragma unroll
            for (int b = 0; b < 2; b++) {
                const float pcx = (pb[b][0] + (float)gi) / (float)SS;
                const float pcy = (pb[b][1] + (float)gj) / (float)SS;
                const float pw = pb[b][2] * pb[b][2], ph = pb[b][3] * pb[b][3];
                const float bx1 = pcx - pw * 0.5f, by1 = pcy - ph * 0.5f;
                const float bx2 = pcx + pw * 0.5f, by2 = pcy + ph * 0.5f;
                const float ix1 = fmaxf(bx1, x1), iy1 = fmaxf(by1, y1);
                const float ix2 = fminf(bx2, x2), iy2 = fminf(by2, y2);
                const float inter = fmaxf(ix2 - ix1, 0.f) * fmaxf(iy2 - iy1, 0.f);
                const float a1 = fmaxf(bx2 - bx1, 0.f) * fmaxf(by2 - by1, 0.f);
                const float a2 = fmaxf(x2 - x1, 0.f) * fmaxf(y2 - y1, 0.f);
                ious[b] = inter / (a1 + a2 - inter + 1e-6f);
            }
            const int best = (ious[1] > ious[0]) ? 1 : 0;   // argmax: first wins on tie
            T.gi[lane] = gi; T.gj[lane] = gj; T.best[lane] = best; T.iou[lane] = ious[best];
            T.cv[lane][0] = cx * (float)SS - (float)gi;
            T.cv[lane][1] = cy * (float)SS - (float)gj;
            T.cv[lane][2] = sqrtf(bw);
            T.cv[lane][3] = sqrtf(bh);
            T.lab[lane] = lab;
        }
    }
    __syncwarp();

    if (active) {
        // ---- phase 2: serial scan, O(1) dedup (lane 0) ----
        if (lane == 0) {
            int np = 0, nc = 0;
            #pragma unroll
            for (int k = 0; k < NGT; k++) {
                const int cell = T.gj[k] * SS + T.gi[k];
                const int pr   = cell * 2 + T.best[k];
                int j;
                const unsigned char h = T.hit[pr];
                if (h) j = h - 1; else { j = np++; T.hit[pr] = (unsigned char)(j + 1); }
                T.conf_t[pr]  = T.iou[k];                 // last-write-wins
                T.coord[j][0] = T.cv[k][0]; T.coord[j][1] = T.cv[k][1];
                T.coord[j][2] = T.cv[k][2]; T.coord[j][3] = T.cv[k][3];
                int e;
                const unsigned char m = T.cellmap[cell];
                if (m) e = m - 1;
                else {
                    e = nc++; T.cellmap[cell] = (unsigned char)(e + 1); T.cell[e] = cell;
                    T.cmask[e][0] = 0u; T.cmask[e][1] = 0u; T.cmask[e][2] = 0u;
                }
                const int l = T.lab[k];
                T.cmask[e][l >> 5] |= (1u << (l & 31));
            }
            T.n_cell = nc;
        }
        __syncwarp();

        // ---- phase 3a: box regions, 5 independent float2 per cell ----
        #pragma unroll 2
        for (int c = lane; c < CELLS; c += 32) {
            const float2* pc2 = reinterpret_cast<const float2*>(p + c * FEAT);
            const float2 v0 = __ldg(pc2 + 0);   // x0 y0
            const float2 v1 = __ldg(pc2 + 1);   // w0 h0
            const float2 v2 = __ldg(pc2 + 2);   // conf0 x1
            const float2 v3 = __ldg(pc2 + 3);   // y1 w1
            const float2 v4 = __ldg(pc2 + 4);   // h1 conf1

            const int h0 = T.hit[2 * c], h1 = T.hit[2 * c + 1];
            const float d0 = v2.x - T.conf_t[2 * c];
            const float d1 = v4.y - T.conf_t[2 * c + 1];
            acc += (h0 ? 1.0f : 0.5f) * d0 * d0;
            acc += (h1 ? 1.0f : 0.5f) * d1 * d1;
            if (h0) {
                const float* cr = T.coord[h0 - 1];
                const float e0 = v0.x - cr[0], e1 = v0.y - cr[1];
                const float e2 = v1.x - cr[2], e3 = v1.y - cr[3];
                acc += 5.0f * (e0 * e0 + e1 * e1 + e2 * e2 + e3 * e3);
            }
            if (h1) {
                const float* cr = T.coord[h1 - 1];
                const float e0 = v2.y - cr[0], e1 = v3.x - cr[1];
                const float e2 = v3.y - cr[2], e3 = v4.x - cr[3];
                acc += 5.0f * (e0 * e0 + e1 * e1 + e2 * e2 + e3 * e3);
            }
        }

        // ---- phase 3b: class terms for object cells (float2) ----
        {
            const int tot = T.n_cell * (NC / 2);
            #pragma unroll 4
            for (int j = lane; j < tot; j += 32) {
                const int e  = j / (NC / 2);
                const int c2 = j - e * (NC / 2);
                const float2 v = __ldg(reinterpret_cast<const float2*>(
                                       p + T.cell[e] * FEAT + NB * 5) + c2);
                const int c0 = 2 * c2;
                const float t0 = ((T.cmask[e][c0 >> 5] >> (c0 & 31)) & 1u) ? 1.0f : 0.0f;
                const float t1 = ((T.cmask[e][(c0 + 1) >> 5] >> ((c0 + 1) & 31)) & 1u) ? 1.0f : 0.0f;
                const float d0 = v.x - t0, d1 = v.y - t1;
                acc += d0 * d0 + d1 * d1;
            }
        }
    }

    // ---- warp reduce, fixed-order block sum (fp64) ----
    #pragma unroll
    for (int o = 16; o; o >>= 1) acc += __shfl_xor_sync(0xFFFFFFFFu, acc, o);
    if (lane == 0) s_part[w] = (double)acc;
    __syncthreads();
    if (threadIdx.x == 0) {
        double s = 0.0;
        #pragma unroll
        for (int i = 0; i < WPB; i++) s += s_part[i];
        g_partials[blockIdx.x] = s;
        __threadfence();
        const unsigned int old = atomicAdd(&g_count, 1u);
        s_last = (old == (unsigned int)(gridDim.x - 1));
    }
    __syncthreads();

    // ---- fused final reduction: elected last block, fixed order ----
    if (s_last) {
        __threadfence();
        const int n = gridDim.x;
        double a = 0.0;
        for (int i = threadIdx.x; i < n; i += TPB) a += g_partials[i];
        __shared__ double s_d[TPB];
        s_d[threadIdx.x] = a;
        __syncthreads();
        #pragma unroll
        for (int s = TPB / 2; s; s >>= 1) {
            if (threadIdx.x < s) s_d[threadIdx.x] += s_d[threadIdx.x + s];
            __syncthreads();
        }
        if (threadIdx.x == 0) {
            out[0] = (float)s_d[0];
            g_count = 0;                 // reset for next graph replay
        }
    }
}

extern "C" void kernel_launch(void* const* d_in, const int* in_sizes, int n_in,
                              void* d_out, int out_size)
{
    const float* preds     = (const float*)d_in[0];
    const float* gt_boxes  = (const float*)d_in[1];
    const int*   gt_labels = (const int*)d_in[2];
    float* out = (float*)d_out;

    int Bsz = in_sizes[0] / (CELLS * FEAT);
    int grid = (Bsz + WPB - 1) / WPB;
    if (grid > MAX_BLK) grid = MAX_BLK;

    yolo_fused<<<grid, TPB>>>(preds, gt_boxes, gt_labels, out, Bsz);
}